// round 3
// baseline (speedup 1.0000x reference)
#include <cuda_runtime.h>
#include <cstdint>

#define B_   64
#define T_   512
#define D_   256
#define H_   256
#define G4_  1024
#define M_   (B_ * T_)   // 32768

// ---------------- scratch (device globals; no allocations allowed) ----------
__device__ float g_xg[(size_t)M_ * G4_];      // [B][T][4H] gate preacts (128MB)
__device__ float g_y1[(size_t)B_ * T_ * H_];  // layer-1 output (32MB)
__device__ float g_masks[6][B_ * H_];         // [layer*3 + {out,h,c}][B*H]

// ---------------- packed fp32x2 helpers -------------------------------------
#define FMA2(acc, a, b) \
  asm("fma.rn.f32x2 %0, %1, %2, %0;" : "+l"(acc) : "l"(a), "l"(b))
#define PACK2(d, s) \
  asm("mov.b64 %0, {%1, %1};" : "=l"(d) : "f"(s))
#define UNPACK2(lo, hi, s) \
  asm("mov.b64 {%0, %1}, %2;" : "=f"(lo), "=f"(hi) : "l"(s))

__device__ __forceinline__ float fast_sigmoid(float x) {
  return __fdividef(1.f, 1.f + __expf(-x));
}
__device__ __forceinline__ float fast_tanh(float x) {
  float a = fabsf(x);
  float e = __expf(-2.f * a);
  float t = __fdividef(1.f - e, 1.f + e);
  return copysignf(t, x);
}

// ---------------- threefry2x32 (exact JAX implementation) -------------------
__device__ __forceinline__ void threefry2x32(uint32_t k0, uint32_t k1,
                                             uint32_t x0, uint32_t x1,
                                             uint32_t& o0, uint32_t& o1) {
  uint32_t ks2 = k0 ^ k1 ^ 0x1BD11BDAu;
#define TF_R(rot) { x0 += x1; x1 = (x1 << (rot)) | (x1 >> (32 - (rot))); x1 ^= x0; }
  x0 += k0; x1 += k1;
  TF_R(13) TF_R(15) TF_R(26) TF_R(6)
  x0 += k1;  x1 += ks2 + 1u;
  TF_R(17) TF_R(29) TF_R(16) TF_R(24)
  x0 += ks2; x1 += k0 + 2u;
  TF_R(13) TF_R(15) TF_R(26) TF_R(6)
  x0 += k0;  x1 += k1 + 3u;
  TF_R(17) TF_R(29) TF_R(16) TF_R(24)
  x0 += k1;  x1 += ks2 + 4u;
  TF_R(13) TF_R(15) TF_R(26) TF_R(6)
  x0 += ks2; x1 += k0 + 5u;
#undef TF_R
  o0 = x0; o1 = x1;
}

__device__ __forceinline__ float mask_val(uint32_t bits) {
  float u = __uint_as_float(0x3f800000u | (bits >> 9)) - 1.0f;
  return (u < 0.75f) ? (1.0f / 0.75f) : 0.0f;
}

// Modern JAX (threefry_partitionable=True):
//   split(key, n)[i] = threefry(key, (0, i))
//   random_bits(key,32,shape)[e]: (b1,b2)=threefry(key,(0,e)); bits=b1^b2
__global__ void mask_kernel() {
  int mid   = blockIdx.y;
  int layer = mid / 3, which = mid % 3;
  int e = blockIdx.x * blockDim.x + threadIdx.x;   // 0..16383

  uint32_t Lk0, Lk1, mk0, mk1, b1, b2;
  threefry2x32(0u, 42u, 0u, (uint32_t)layer, Lk0, Lk1);
  threefry2x32(Lk0, Lk1, 0u, (uint32_t)which, mk0, mk1);
  threefry2x32(mk0, mk1, 0u, (uint32_t)e, b1, b2);
  g_masks[mid][e] = mask_val(b1 ^ b2);
}

// ---------------- input-projection GEMM: Y[m][n] = X[m,:]·W[n,:] + bias -----
// X: [M,256] row-major, W: [1024,256] row-major, Y: [M,1024]
__global__ void __launch_bounds__(256) gemm_xg_kernel(
    const float* __restrict__ X, const float* __restrict__ W,
    const float* __restrict__ bi, const float* __restrict__ bh,
    float* __restrict__ Y) {
  const int K = 256, N = 1024;
  __shared__ float As[32][132];   // [kk][mm], padded
  __shared__ float Bs[32][132];   // [kk][nn], padded
  int bm = blockIdx.y * 128, bn = blockIdx.x * 128;
  int tid = threadIdx.x;
  int tx = tid & 15, ty = tid >> 4;

  uint64_t acc[8][4];             // [i][jpair] packed f32x2
#pragma unroll
  for (int i = 0; i < 8; i++)
#pragma unroll
    for (int j = 0; j < 4; j++) acc[i][j] = 0ull;

  for (int k0 = 0; k0 < K; k0 += 32) {
#pragma unroll
    for (int i = 0; i < 4; i++) {
      int idx = tid + i * 256;
      int row = idx >> 3;
      int kk  = (idx & 7) << 2;
      float4 va = *(const float4*)&X[(size_t)(bm + row) * K + k0 + kk];
      As[kk + 0][row] = va.x; As[kk + 1][row] = va.y;
      As[kk + 2][row] = va.z; As[kk + 3][row] = va.w;
      float4 vb = *(const float4*)&W[(size_t)(bn + row) * K + k0 + kk];
      Bs[kk + 0][row] = vb.x; Bs[kk + 1][row] = vb.y;
      Bs[kk + 2][row] = vb.z; Bs[kk + 3][row] = vb.w;
    }
    __syncthreads();
#pragma unroll
    for (int kk = 0; kk < 32; kk++) {
      float4 a0 = *(const float4*)&As[kk][ty * 8];
      float4 a1 = *(const float4*)&As[kk][ty * 8 + 4];
      ulonglong2 b0 = *(const ulonglong2*)&Bs[kk][tx * 8];
      ulonglong2 b1 = *(const ulonglong2*)&Bs[kk][tx * 8 + 4];
      float av[8] = {a0.x, a0.y, a0.z, a0.w, a1.x, a1.y, a1.z, a1.w};
#pragma unroll
      for (int i = 0; i < 8; i++) {
        uint64_t ap;
        PACK2(ap, av[i]);
        FMA2(acc[i][0], ap, b0.x);
        FMA2(acc[i][1], ap, b0.y);
        FMA2(acc[i][2], ap, b1.x);
        FMA2(acc[i][3], ap, b1.y);
      }
    }
    __syncthreads();
  }

  float bias[8];
#pragma unroll
  for (int j = 0; j < 8; j++) {
    int n = bn + tx * 8 + j;
    bias[j] = bi[n] + bh[n];
  }
#pragma unroll
  for (int i = 0; i < 8; i++) {
    float c[8];
#pragma unroll
    for (int j = 0; j < 4; j++) UNPACK2(c[2 * j], c[2 * j + 1], acc[i][j]);
    size_t base = (size_t)(bm + ty * 8 + i) * N + bn + tx * 8;
    float4 v0 = make_float4(c[0] + bias[0], c[1] + bias[1],
                            c[2] + bias[2], c[3] + bias[3]);
    float4 v1 = make_float4(c[4] + bias[4], c[5] + bias[5],
                            c[6] + bias[6], c[7] + bias[7]);
    *(float4*)&Y[base]     = v0;
    *(float4*)&Y[base + 4] = v1;
  }
}

// ---------------- persistent recurrent LSTM layer ---------------------------
// Cluster of 8 CTAs per 4 batch elements. CTA rank s owns hidden units
// [32s, 32s+32) for all 4 gates (128 weight rows, smem-resident, [k][r] layout).
#define LSTM_SMEM_FLOATS (256 * 129 + 2 * 256 * 4 + 4 * 128 * 4)
#define LSTM_SMEM_BYTES  (LSTM_SMEM_FLOATS * 4)

__global__ void __launch_bounds__(512, 1) __cluster_dims__(8, 1, 1)
lstm_layer_kernel(const float* __restrict__ xg, const float* __restrict__ Whh,
                  const float* __restrict__ mask_out,
                  const float* __restrict__ mask_h,
                  const float* __restrict__ mask_c,
                  float* __restrict__ out) {
  extern __shared__ float smem[];
  float* wT   = smem;                 // [256][129]  (k-major, pad 129)
  float* hbuf = wT + 256 * 129;       // [2][256][4] (k-major x batch)
  float* part = hbuf + 2 * 256 * 4;   // [4][128][4] (kq, row, batch)

  int tid = threadIdx.x;
  uint32_t s;
  asm("mov.u32 %0, %%cluster_ctarank;" : "=r"(s));
  int b_base = (blockIdx.x >> 3) * 4;

  int kq = tid >> 7;          // k-quarter 0..3
  int r  = tid & 127;         // local gate-row (gate = r>>5, unit = r&31)

  // load weight slice transposed into smem
  for (int idx = tid; idx < 128 * 256; idx += 512) {
    int rr = idx >> 8;
    int k  = idx & 255;
    int gr = ((rr >> 5) << 8) + ((int)s << 5) + (rr & 31);
    wT[k * 129 + rr] = Whh[(size_t)gr * 256 + k];
  }
  for (int idx = tid; idx < 2 * 256 * 4; idx += 512) hbuf[idx] = 0.f;

  // finalize-role (tid < 128): one (unit u, batch b) pair each
  float c_state = 0.f, mo = 0.f, mh = 0.f, mc = 0.f;
  int u = tid >> 2;
  size_t out_base = 0;
  const float* xg_base = nullptr;
  uint32_t haddr[2][8];
  if (tid < 128) {
    int b = tid & 3;
    int bb = b_base + b;
    int unit = (int)s * 32 + u;
    mo = mask_out[bb * 256 + unit];
    mh = mask_h  [bb * 256 + unit];
    mc = mask_c  [bb * 256 + unit];
    out_base = (size_t)bb * (T_ * H_) + unit;
    xg_base  = xg + (size_t)bb * (T_ * G4_) + unit;   // + t*G4 + gate*256
#pragma unroll
    for (int par = 0; par < 2; par++) {
      uint32_t laddr =
          (uint32_t)__cvta_generic_to_shared(&hbuf[par * 1024 + unit * 4 + b]);
#pragma unroll
      for (int rk = 0; rk < 8; rk++) {
        uint32_t ra;
        asm("mapa.shared::cluster.u32 %0, %1, %2;" : "=r"(ra) : "r"(laddr), "r"(rk));
        haddr[par][rk] = ra;
      }
    }
  }

  asm volatile("barrier.cluster.arrive.aligned;" ::: "memory");
  asm volatile("barrier.cluster.wait.aligned;"   ::: "memory");

  const float* wk = wT + (kq * 64) * 129 + r;
  int par = 0;

  for (int t = 0; t < T_; t++) {
    // prefetch this step's gate preacts (finalize threads only) — consumed
    // after the matmul + syncthreads, so DRAM/L2 latency is hidden.
    float xvi = 0.f, xvf = 0.f, xvg = 0.f, xvo = 0.f;
    if (tid < 128) {
      const float* xp = xg_base + (size_t)t * G4_;
      xvi = xp[0];
      xvf = xp[256];
      xvg = xp[512];
      xvo = xp[768];
    }

    // partial dot over this thread's k-quarter (64 k), 4 batches packed f32x2
    const ulonglong2* hb =
        (const ulonglong2*)(hbuf + par * 1024 + kq * 256);
    uint64_t a01 = 0ull, a23 = 0ull;
#pragma unroll 8
    for (int k0 = 0; k0 < 64; k0++) {
      float w = wk[k0 * 129];
      uint64_t wd;
      PACK2(wd, w);
      ulonglong2 h2 = hb[k0];
      FMA2(a01, wd, h2.x);
      FMA2(a23, wd, h2.y);
    }
    *(ulonglong2*)&part[(kq * 128 + r) * 4] = make_ulonglong2(a01, a23);
    __syncthreads();

    if (tid < 128) {
      int b = tid & 3;
      float gi = xvi, gf = xvf, gg = xvg, go = xvo;
#pragma unroll
      for (int q2 = 0; q2 < 4; q2++) {
        const float* pp = part + q2 * 512;
        gi += pp[(u)      * 4 + b];
        gf += pp[(32 + u) * 4 + b];
        gg += pp[(64 + u) * 4 + b];
        go += pp[(96 + u) * 4 + b];
      }
      float ig = fast_sigmoid(gi);
      float fg = fast_sigmoid(gf);
      float og = fast_sigmoid(go);
      float gt = fast_tanh(gg);
      c_state = fg * c_state + ig * gt;
      float h = og * fast_tanh(c_state);
      c_state *= mc;                            // variational cell mask
      out[out_base + (size_t)t * H_] = h * mo;  // output mask
      float hm = h * mh;                        // carry mask
#pragma unroll
      for (int rk = 0; rk < 8; rk++)
        asm volatile("st.shared::cluster.f32 [%0], %1;"
                     :: "r"(haddr[par ^ 1][rk]), "f"(hm) : "memory");
    }
    asm volatile("barrier.cluster.arrive.aligned;" ::: "memory");
    asm volatile("barrier.cluster.wait.aligned;"   ::: "memory");
    par ^= 1;
  }
}

// ---------------- launcher ---------------------------------------------------
extern "C" void kernel_launch(void* const* d_in, const int* in_sizes, int n_in,
                              void* d_out, int out_size) {
  const float* x     = (const float*)d_in[0];
  const float* W_ih0 = (const float*)d_in[1];
  const float* W_hh0 = (const float*)d_in[2];
  const float* b_ih0 = (const float*)d_in[3];
  const float* b_hh0 = (const float*)d_in[4];
  const float* W_ih1 = (const float*)d_in[5];
  const float* W_hh1 = (const float*)d_in[6];
  const float* b_ih1 = (const float*)d_in[7];
  const float* b_hh1 = (const float*)d_in[8];
  float* out = (float*)d_out;

  float *xg, *y1, *masks;
  cudaGetSymbolAddress((void**)&xg, g_xg);
  cudaGetSymbolAddress((void**)&y1, g_y1);
  cudaGetSymbolAddress((void**)&masks, g_masks);

  cudaFuncSetAttribute(lstm_layer_kernel,
                       cudaFuncAttributeMaxDynamicSharedMemorySize,
                       LSTM_SMEM_BYTES);

  mask_kernel<<<dim3(64, 6), 256>>>();

  gemm_xg_kernel<<<dim3(8, 256), 256>>>(x, W_ih0, b_ih0, b_hh0, xg);
  lstm_layer_kernel<<<128, 512, LSTM_SMEM_BYTES>>>(
      xg, W_hh0, masks + 0 * 16384, masks + 1 * 16384, masks + 2 * 16384, y1);

  gemm_xg_kernel<<<dim3(8, 256), 256>>>(y1, W_ih1, b_ih1, b_hh1, xg);
  lstm_layer_kernel<<<128, 512, LSTM_SMEM_BYTES>>>(
      xg, W_hh1, masks + 3 * 16384, masks + 4 * 16384, masks + 5 * 16384, out);
}